// round 2
// baseline (speedup 1.0000x reference)
#include <cuda_runtime.h>
#include <math.h>

// Problem constants
#define NROWS 16384          // 32*512
#define H     768
#define NB    8              // NUM_BASIS
#define KEXP  (H * 9)        // 6912 expanded K (silu + 8 bases per input)
#define LOUT  2

// GEMM tiling
#define BM 128
#define BN 128
#define BK 72                // 8 inputs * 9 channels; 9 mma k-steps of 8
#define KTILES (KEXP / BK)   // 96
#define PAD 76               // smem row pitch (conflict-free for frag loads)
#define SMEM_BYTES ((BM + BN) * PAD * 4)   // 77824

// Device scratch (no allocation allowed)
__device__ float  g_W1c[H * KEXP];     // combined layer-1 weights, [o][k], tf32-rounded (21.2 MB)
__device__ float  g_Y[NROWS * H];      // layer-1 output after GELU (50.3 MB)
__device__ float2 g_W2c[KEXP];         // combined layer-2 weights, [k] -> (l0, l1)

// ---------------------------------------------------------------------------
// helpers
// ---------------------------------------------------------------------------
__device__ __forceinline__ unsigned f2tf32(float x) {
    unsigned r;
    asm("cvt.rna.tf32.f32 %0, %1;" : "=r"(r) : "f"(x));
    return r;
}

__device__ __forceinline__ float siluf(float x) {
    return x / (1.0f + __expf(-x));
}

__device__ __forceinline__ float geluf(float x) {
    // exact erf gelu (approximate=False)
    return 0.5f * x * (1.0f + erff(x * 0.70710678118654752f));
}

// v[0] = silu(x); v[1..8] = cubic B-spline bases B_{0..7,3}(x)
// knots t_j = -2.2 + 0.4*j, j=0..11. For x in [t_k, t_{k+1}), bases j=k-3..k
// take the standard uniform cubic values; only j in [0,7] kept.
__device__ __forceinline__ void expand9(float x, float* v) {
    v[0] = siluf(x);
#pragma unroll
    for (int j = 1; j < 9; j++) v[j] = 0.0f;
    float t  = (x + 2.2f) * 2.5f;
    float kf = floorf(t);
    int   k  = (int)kf;
    if (k >= 0 && k <= 10) {
        float u  = t - kf;
        float u2 = u * u, u3 = u2 * u;
        float om = 1.0f - u;
        float b0 = om * om * om * (1.0f / 6.0f);                       // j = k-3
        float b1 = (4.0f - 6.0f * u2 + 3.0f * u3) * (1.0f / 6.0f);     // j = k-2
        float b2 = (1.0f + 3.0f * u + 3.0f * u2 - 3.0f * u3) * (1.0f / 6.0f); // j = k-1
        float b3 = u3 * (1.0f / 6.0f);                                  // j = k
        int j0 = k - 3;
        if (j0     >= 0 && j0     <= 7) v[1 + j0]     = b0;
        if (j0 + 1 >= 0 && j0 + 1 <= 7) v[1 + j0 + 1] = b1;
        if (j0 + 2 >= 0 && j0 + 2 <= 7) v[1 + j0 + 2] = b2;
        if (j0 + 3 >= 0 && j0 + 3 <= 7) v[1 + j0 + 3] = b3;
    }
}

// ---------------------------------------------------------------------------
// weight prep kernels (recomputed every call: deterministic, trivially cheap)
// ---------------------------------------------------------------------------
__global__ void prep_w1(const float* __restrict__ bw,
                        const float* __restrict__ sw,
                        const float* __restrict__ sc) {
    int idx = blockIdx.x * blockDim.x + threadIdx.x;   // over H*H (o,i)
    if (idx >= H * H) return;
    int o = idx / H, i = idx % H;
    float* dst = &g_W1c[(size_t)o * KEXP + i * 9];
    dst[0] = __uint_as_float(f2tf32(bw[idx]));
    float s = sc[idx];
#pragma unroll
    for (int g = 0; g < 8; g++)
        dst[1 + g] = __uint_as_float(f2tf32(sw[(size_t)idx * 8 + g] * s));
}

__global__ void prep_w2(const float* __restrict__ bw,
                        const float* __restrict__ sw,
                        const float* __restrict__ sc) {
    int i = blockIdx.x * blockDim.x + threadIdx.x;
    if (i >= H) return;
    float s0 = sc[0 * H + i], s1 = sc[1 * H + i];
    float2 v;
    v.x = bw[0 * H + i];
    v.y = bw[1 * H + i];
    g_W2c[i * 9] = v;
#pragma unroll
    for (int g = 0; g < 8; g++) {
        v.x = sw[((size_t)(0 * H + i)) * 8 + g] * s0;
        v.y = sw[((size_t)(1 * H + i)) * 8 + g] * s1;
        g_W2c[i * 9 + 1 + g] = v;
    }
}

// ---------------------------------------------------------------------------
// Layer-1 fused GEMM: C[N,768] = expand(x)[N,6912] @ W1c^T, epilogue = GELU
// tf32 mma.sync m16n8k8, CTA tile 128x128, 8 warps (4m x 2n), warp tile 32x64.
// A operand is computed on the fly from x (no 452MB intermediate).
// ---------------------------------------------------------------------------
__device__ __forceinline__ void mma_tf32(float* c, const unsigned* a,
                                         unsigned b0, unsigned b1) {
    asm volatile(
        "mma.sync.aligned.m16n8k8.row.col.f32.tf32.tf32.f32 "
        "{%0,%1,%2,%3}, {%4,%5,%6,%7}, {%8,%9}, {%0,%1,%2,%3};\n"
        : "+f"(c[0]), "+f"(c[1]), "+f"(c[2]), "+f"(c[3])
        : "r"(a[0]), "r"(a[1]), "r"(a[2]), "r"(a[3]), "r"(b0), "r"(b1));
}

__global__ void __launch_bounds__(256, 2)
gemm1_fused(const float* __restrict__ x) {
    extern __shared__ float smem[];
    float* As = smem;                 // [BM][PAD]
    float* Bs = smem + BM * PAD;      // [BN][PAD]

    const int m0   = blockIdx.y * BM;
    const int n0   = blockIdx.x * BN;
    const int tid  = threadIdx.x;
    const int warp = tid >> 5, lane = tid & 31;
    const int wm = warp & 3;          // 0..3 -> m offset wm*32
    const int wn = warp >> 2;         // 0..1 -> n offset wn*64
    const int g  = lane >> 2;         // group id
    const int tg = lane & 3;          // thread in group

    float c[2][8][4];
#pragma unroll
    for (int mt = 0; mt < 2; mt++)
#pragma unroll
        for (int nt = 0; nt < 8; nt++)
#pragma unroll
            for (int q = 0; q < 4; q++) c[mt][nt][q] = 0.0f;

    for (int kt = 0; kt < KTILES; kt++) {
        // ---- producer: expand A tile (128 rows x 8 inputs -> 72 k-cols) ----
        const int ibase = kt * 8;
#pragma unroll
        for (int rep = 0; rep < 4; rep++) {
            int p  = tid + rep * 256;        // 0..1023
            int il = p & 7, nl = p >> 3;
            float xv = x[(size_t)(m0 + nl) * H + ibase + il];
            float v[9];
            expand9(xv, v);
            float* dst = &As[nl * PAD + il * 9];
#pragma unroll
            for (int j = 0; j < 9; j++)
                dst[j] = __uint_as_float(f2tf32(v[j]));
        }
        // ---- producer: load B tile (128 outputs x 72 k), already tf32 ----
        const float* Bsrc = &g_W1c[(size_t)n0 * KEXP + kt * BK];
#pragma unroll
        for (int rep = 0; rep < 9; rep++) {
            int p  = tid + rep * 256;        // 0..2303 (float4 units)
            int ol = p / 18, kk = (p % 18) * 4;   // 72 floats = 18 float4 per row
            float4 val = *reinterpret_cast<const float4*>(&Bsrc[(size_t)ol * KEXP + kk]);
            *reinterpret_cast<float4*>(&Bs[ol * PAD + kk]) = val;
        }
        __syncthreads();

        // ---- consumer: 9 mma k-steps of 8 ----
#pragma unroll
        for (int ks = 0; ks < 9; ks++) {
            const int kk0 = ks * 8;
            unsigned a[2][4];
#pragma unroll
            for (int mt = 0; mt < 2; mt++) {
                const float* ap = &As[(wm * 32 + mt * 16 + g) * PAD + kk0 + tg];
                a[mt][0] = __float_as_uint(ap[0]);
                a[mt][1] = __float_as_uint(ap[8 * PAD]);
                a[mt][2] = __float_as_uint(ap[4]);
                a[mt][3] = __float_as_uint(ap[8 * PAD + 4]);
            }
#pragma unroll
            for (int nt = 0; nt < 8; nt++) {
                const float* bp = &Bs[(wn * 64 + nt * 8 + g) * PAD + kk0 + tg];
                unsigned b0 = __float_as_uint(bp[0]);
                unsigned b1 = __float_as_uint(bp[4]);
#pragma unroll
                for (int mt = 0; mt < 2; mt++)
                    mma_tf32(c[mt][nt], a[mt], b0, b1);
            }
        }
        __syncthreads();
    }

    // ---- epilogue: GELU(erf) + store ----
#pragma unroll
    for (int mt = 0; mt < 2; mt++) {
#pragma unroll
        for (int nt = 0; nt < 8; nt++) {
            int r   = m0 + wm * 32 + mt * 16 + g;
            int col = n0 + wn * 64 + nt * 8 + 2 * tg;
            float2 v0, v1;
            v0.x = geluf(c[mt][nt][0]);
            v0.y = geluf(c[mt][nt][1]);
            v1.x = geluf(c[mt][nt][2]);
            v1.y = geluf(c[mt][nt][3]);
            *reinterpret_cast<float2*>(&g_Y[(size_t)r * H + col])       = v0;
            *reinterpret_cast<float2*>(&g_Y[(size_t)(r + 8) * H + col]) = v1;
        }
    }
}

// ---------------------------------------------------------------------------
// Layer-2: out[N,2] = expand(gelu_y)[N,6912] @ W2c. One warp per row.
// ---------------------------------------------------------------------------
__global__ void kan2(float* __restrict__ out) {
    const int tid = threadIdx.x;
    const int warp = tid >> 5, lane = tid & 31;
    const int row = blockIdx.x * 8 + warp;

    float a0 = 0.0f, a1 = 0.0f;
#pragma unroll 4
    for (int i = lane; i < H; i += 32) {
        float y = g_Y[(size_t)row * H + i];
        float v[9];
        expand9(y, v);
        const float2* w = &g_W2c[i * 9];
#pragma unroll
        for (int j = 0; j < 9; j++) {
            float2 wj = __ldg(&w[j]);
            a0 += v[j] * wj.x;
            a1 += v[j] * wj.y;
        }
    }
#pragma unroll
    for (int off = 16; off > 0; off >>= 1) {
        a0 += __shfl_down_sync(0xffffffffu, a0, off);
        a1 += __shfl_down_sync(0xffffffffu, a1, off);
    }
    if (lane == 0) {
        out[row * 2 + 0] = a0;
        out[row * 2 + 1] = a1;
    }
}

// ---------------------------------------------------------------------------
extern "C" void kernel_launch(void* const* d_in, const int* in_sizes, int n_in,
                              void* d_out, int out_size) {
    const float* hidden = (const float*)d_in[0];
    const float* bw1    = (const float*)d_in[1];
    const float* sw1    = (const float*)d_in[2];
    const float* sc1    = (const float*)d_in[3];
    const float* bw2    = (const float*)d_in[4];
    const float* sw2    = (const float*)d_in[5];
    const float* sc2    = (const float*)d_in[6];
    float* out = (float*)d_out;

    cudaFuncSetAttribute(gemm1_fused,
                         cudaFuncAttributeMaxDynamicSharedMemorySize, SMEM_BYTES);

    prep_w1<<<(H * H + 255) / 256, 256>>>(bw1, sw1, sc1);
    prep_w2<<<(H + 255) / 256, 256>>>(bw2, sw2, sc2);
    gemm1_fused<<<dim3(H / BN, NROWS / BM), 256, SMEM_BYTES>>>(hidden);
    kan2<<<NROWS / 8, 256>>>(out);
}

// round 4
// speedup vs baseline: 1.0799x; 1.0799x over previous
#include <cuda_runtime.h>
#include <cuda_fp16.h>
#include <cstdint>
#include <math.h>

#define NROWS 16384
#define H     768
#define KEXP  6912            // 768 inputs * 9 channels (silu + 8 bases)
#define BM    128
#define BN    256
#define BK    64
#define NKT   (KEXP / BK)     // 108
#define PITCH 72              // halfs per smem row (144 B) — conflict-free
#define ASTG  (BM * PITCH)    // halfs
#define BSTG  (BN * PITCH)
#define STGH  (ASTG + BSTG)   // halfs per stage (55296 B)
#define NSTAGE 3
#define SMEMSZ (NSTAGE * STGH * 2)   // 165888 B
#define NTILE  (H / BN)       // 3
#define NSLICES 48            // partials per row: ntile(3) * wn(4) * tg(4)

// ---------------- device scratch (static; no allocation allowed) ----------
__device__ __align__(16) __half g_Aexp[(size_t)NROWS * KEXP];  // 226 MB
__device__ __align__(16) __half g_W1h[(size_t)H * KEXP];       // 10.6 MB
__device__ float2 g_W2c[H * 9];
__device__ float2 g_part[(size_t)NROWS * NSLICES];             // 6.3 MB

// ---------------- helpers ----------------
__device__ __forceinline__ float siluf(float x) { return x / (1.0f + __expf(-x)); }
__device__ __forceinline__ float geluf(float x) {
    return 0.5f * x * (1.0f + erff(x * 0.70710678118654752f));
}

// v[0] = silu(x); v[1..8] = cubic B-spline bases (knots -2.2 + 0.4j).
// Branchless: constant-indexed writes only (stays in registers).
__device__ __forceinline__ void expand9(float x, float v[9]) {
    v[0] = siluf(x);
    float t  = (x + 2.2f) * 2.5f;
    float kf = floorf(t);
    int   k  = (int)kf;
    float u  = t - kf, u2 = u * u, u3 = u2 * u, om = 1.0f - u;
    bool ok = (k >= 0) && (k <= 10);
    float b0 = om * om * om * (1.0f / 6.0f);
    float b1 = (4.0f - 6.0f * u2 + 3.0f * u3) * (1.0f / 6.0f);
    float b2 = (1.0f + 3.0f * u + 3.0f * u2 - 3.0f * u3) * (1.0f / 6.0f);
    float b3 = u3 * (1.0f / 6.0f);
    int j0 = k - 3;
#pragma unroll
    for (int j = 0; j < 8; j++) {
        int d = j - j0;
        float bv = (d == 0) ? b0 : (d == 1) ? b1 : (d == 2) ? b2 : (d == 3) ? b3 : 0.0f;
        v[1 + j] = ok ? bv : 0.0f;
    }
}

__device__ __forceinline__ uint32_t smem_u32(const void* p) {
    uint32_t a;
    asm("{ .reg .u64 t; cvta.to.shared.u64 t, %1; cvt.u32.u64 %0, t; }" : "=r"(a) : "l"(p));
    return a;
}

__device__ __forceinline__ void cp16(uint32_t dst, const void* gsrc) {
    size_t p = __cvta_generic_to_global(const_cast<void*>(gsrc));
    asm volatile("cp.async.cg.shared.global [%0], [%1], 16;" :: "r"(dst), "l"(p) : "memory");
}
#define CP_COMMIT() asm volatile("cp.async.commit_group;" ::: "memory")
#define CP_WAIT2()  asm volatile("cp.async.wait_group 2;" ::: "memory")

__device__ __forceinline__ void mma_f16(float* c, const unsigned* a,
                                        unsigned b0, unsigned b1) {
    asm volatile(
        "mma.sync.aligned.m16n8k16.row.col.f32.f16.f16.f32 "
        "{%0,%1,%2,%3}, {%4,%5,%6,%7}, {%8,%9}, {%0,%1,%2,%3};\n"
        : "+f"(c[0]), "+f"(c[1]), "+f"(c[2]), "+f"(c[3])
        : "r"(a[0]), "r"(a[1]), "r"(a[2]), "r"(a[3]), "r"(b0), "r"(b1));
}

// ---------------- prep kernels ----------------
__global__ void prep_w1h(const float* __restrict__ bw, const float* __restrict__ sw,
                         const float* __restrict__ sc) {
    int idx = blockIdx.x * 256 + threadIdx.x;   // o*H + i
    if (idx >= H * H) return;
    __half* dst = &g_W1h[(size_t)idx * 9];      // == o*KEXP + i*9
    dst[0] = __float2half_rn(bw[idx]);
    float s = sc[idx];
#pragma unroll
    for (int j = 0; j < 8; j++)
        dst[1 + j] = __float2half_rn(sw[(size_t)idx * 8 + j] * s);
}

__global__ void prep_w2(const float* __restrict__ bw, const float* __restrict__ sw,
                        const float* __restrict__ sc) {
    int i = blockIdx.x * 256 + threadIdx.x;
    if (i >= H) return;
    float s0 = sc[i], s1 = sc[H + i];
    g_W2c[i * 9] = make_float2(bw[i], bw[H + i]);
#pragma unroll
    for (int j = 0; j < 8; j++)
        g_W2c[i * 9 + 1 + j] = make_float2(sw[(size_t)i * 8 + j] * s0,
                                           sw[(size_t)(H + i) * 8 + j] * s1);
}

// ---------------- one-time spline expansion of the input ----------------
__global__ void expand_a(const float* __restrict__ x) {
    int idx = blockIdx.x * 256 + threadIdx.x;   // row*H + i
    float v[9];
    expand9(x[idx], v);
    __half* dst = &g_Aexp[(size_t)idx * 9];
#pragma unroll
    for (int j = 0; j < 9; j++) dst[j] = __float2half_rn(v[j]);
}

// ---------------- fused GEMM: layer1 + GELU + layer2-partials ----------------
__global__ void __launch_bounds__(256, 1) gemm_fused() {
    extern __shared__ __half sm[];
    const uint32_t sb = smem_u32(sm);
    const int tid = threadIdx.x, wid = tid >> 5, lane = tid & 31;
    const int g = lane >> 2, tg = lane & 3;
    const int wm = wid & 1, wn = wid >> 1;          // warp grid 2m x 4n, warp tile 64x64
    const int m0 = blockIdx.y * BM, n0 = blockIdx.x * BN;

    float c[4][8][4];
#pragma unroll
    for (int mt = 0; mt < 4; mt++)
#pragma unroll
        for (int nt = 0; nt < 8; nt++)
#pragma unroll
            for (int q = 0; q < 4; q++) c[mt][nt][q] = 0.0f;

    auto issue = [&](int kt) {
        const int s = kt % NSTAGE;
        const uint32_t abase = sb + s * (STGH * 2);
        const __half* asrc = g_Aexp + (size_t)m0 * KEXP + kt * BK;
#pragma unroll
        for (int r = 0; r < 4; r++) {
            int ch = tid + r * 256;                 // 1024 chunks of 16B
            int row = ch >> 3, col = ch & 7;
            cp16(abase + row * 144 + col * 16, asrc + (size_t)row * KEXP + col * 8);
        }
        const uint32_t bbase = abase + ASTG * 2;
        const __half* bsrc = g_W1h + (size_t)n0 * KEXP + kt * BK;
#pragma unroll
        for (int r = 0; r < 8; r++) {
            int ch = tid + r * 256;                 // 2048 chunks
            int row = ch >> 3, col = ch & 7;
            cp16(bbase + row * 144 + col * 16, bsrc + (size_t)row * KEXP + col * 8);
        }
    };

    issue(0); CP_COMMIT();
    issue(1); CP_COMMIT();

    for (int kt = 0; kt < NKT; kt++) {
        if (kt + 2 < NKT) issue(kt + 2);
        CP_COMMIT();
        CP_WAIT2();
        __syncthreads();
        const __half* As = sm + (kt % NSTAGE) * STGH;
        const __half* Bs = As + ASTG;
#pragma unroll
        for (int ks = 0; ks < 4; ks++) {
            const int k0 = ks * 16;
            unsigned a[4][4];
#pragma unroll
            for (int mt = 0; mt < 4; mt++) {
                const __half* ap = As + (wm * 64 + mt * 16 + g) * PITCH + k0 + 2 * tg;
                a[mt][0] = *(const unsigned*)ap;
                a[mt][1] = *(const unsigned*)(ap + 8 * PITCH);
                a[mt][2] = *(const unsigned*)(ap + 8);
                a[mt][3] = *(const unsigned*)(ap + 8 * PITCH + 8);
            }
#pragma unroll
            for (int nt = 0; nt < 8; nt++) {
                const __half* bp = Bs + (wn * 64 + nt * 8 + g) * PITCH + k0 + 2 * tg;
                unsigned b0 = *(const unsigned*)bp;
                unsigned b1 = *(const unsigned*)(bp + 8);
#pragma unroll
                for (int mt = 0; mt < 4; mt++)
                    mma_f16(c[mt][nt], a[mt], b0, b1);
            }
        }
        __syncthreads();
    }

    // epilogue: gelu + spline-expand + layer-2 partial dot (fp32)
    const int slice = blockIdx.x * 16 + wn * 4 + tg;
#pragma unroll
    for (int mt = 0; mt < 4; mt++) {
#pragma unroll
        for (int hq = 0; hq < 2; hq++) {
            int row = m0 + wm * 64 + mt * 16 + g + hq * 8;
            float p0 = 0.0f, p1 = 0.0f;
#pragma unroll
            for (int nt = 0; nt < 8; nt++) {
#pragma unroll
                for (int par = 0; par < 2; par++) {
                    float y = geluf(c[mt][nt][hq * 2 + par]);
                    int col = n0 + wn * 64 + nt * 8 + 2 * tg + par;
                    float v[9];
                    expand9(y, v);
                    const float2* w = &g_W2c[col * 9];
#pragma unroll
                    for (int j = 0; j < 9; j++) {
                        float2 wj = __ldg(&w[j]);
                        p0 = fmaf(v[j], wj.x, p0);
                        p1 = fmaf(v[j], wj.y, p1);
                    }
                }
            }
            g_part[(size_t)row * NSLICES + slice] = make_float2(p0, p1);
        }
    }
}

// ---------------- final reduce ----------------
__global__ void reduce2(float* __restrict__ out) {
    int row = blockIdx.x * 256 + threadIdx.x;
    if (row >= NROWS) return;
    const float2* p = &g_part[(size_t)row * NSLICES];
    float a = 0.0f, b = 0.0f;
#pragma unroll
    for (int s = 0; s < NSLICES; s++) { float2 v = p[s]; a += v.x; b += v.y; }
    out[row * 2 + 0] = a;
    out[row * 2 + 1] = b;
}

// ---------------------------------------------------------------------------
extern "C" void kernel_launch(void* const* d_in, const int* in_sizes, int n_in,
                              void* d_out, int out_size) {
    const float* hidden = (const float*)d_in[0];
    const float* bw1 = (const float*)d_in[1];
    const float* sw1 = (const float*)d_in[2];
    const float* sc1 = (const float*)d_in[3];
    const float* bw2 = (const float*)d_in[4];
    const float* sw2 = (const float*)d_in[5];
    const float* sc2 = (const float*)d_in[6];
    float* out = (float*)d_out;

    cudaFuncSetAttribute(gemm_fused, cudaFuncAttributeMaxDynamicSharedMemorySize, SMEMSZ);

    prep_w1h<<<(H * H + 255) / 256, 256>>>(bw1, sw1, sc1);
    prep_w2<<<(H + 255) / 256, 256>>>(bw2, sw2, sc2);
    expand_a<<<(NROWS * H) / 256, 256>>>(hidden);
    gemm_fused<<<dim3(NTILE, NROWS / BM), 256, SMEMSZ>>>();
    reduce2<<<NROWS / 256, 256>>>(out);
}

// round 5
// speedup vs baseline: 1.5940x; 1.4761x over previous
#include <cuda_runtime.h>
#include <cuda_fp16.h>
#include <cstdint>
#include <math.h>

#define NROWS 16384
#define H     768
#define KEXP  6912            // 768 inputs * 9 channels (silu + 8 bases)
#define BM    128
#define BN    128
#define BK    64
#define NKT   (KEXP / BK)     // 108
#define PITCH 72              // halfs per smem row (144 B) — conflict-free
#define ROWB  144             // bytes per smem row
#define ASTGB (BM * ROWB)     // 18432 B
#define BSTGB (BN * ROWB)     // 18432 B
#define STGB  (ASTGB + BSTGB) // 36864 B per stage
#define NSTAGE 3
#define SMEMSZ (NSTAGE * STGB)   // 110592 B  -> 2 CTAs/SM
#define NTILE  (H / BN)       // 6
#define NSLICES 48            // partials per row: ntile(6) * wn(2) * tg(4)

// ---------------- device scratch (static; no allocation allowed) ----------
__device__ __align__(16) __half g_Aexp[(size_t)NROWS * KEXP];  // 226 MB
__device__ __align__(16) __half g_W1h[(size_t)H * KEXP];       // 10.6 MB
__device__ float2 g_W2c[H * 9];
__device__ float2 g_part[(size_t)NROWS * NSLICES];             // 6.3 MB

// ---------------- helpers ----------------
__device__ __forceinline__ float siluf(float x) { return x / (1.0f + __expf(-x)); }
__device__ __forceinline__ float geluf(float x) {
    return 0.5f * x * (1.0f + erff(x * 0.70710678118654752f));
}

// v[0] = silu(x); v[1..8] = cubic B-spline bases (knots -2.2 + 0.4j). Branchless.
__device__ __forceinline__ void expand9(float x, float v[9]) {
    v[0] = siluf(x);
    float t  = (x + 2.2f) * 2.5f;
    float kf = floorf(t);
    int   k  = (int)kf;
    float u  = t - kf, u2 = u * u, u3 = u2 * u, om = 1.0f - u;
    bool ok = (k >= 0) && (k <= 10);
    float b0 = om * om * om * (1.0f / 6.0f);
    float b1 = (4.0f - 6.0f * u2 + 3.0f * u3) * (1.0f / 6.0f);
    float b2 = (1.0f + 3.0f * u + 3.0f * u2 - 3.0f * u3) * (1.0f / 6.0f);
    float b3 = u3 * (1.0f / 6.0f);
    int j0 = k - 3;
#pragma unroll
    for (int j = 0; j < 8; j++) {
        int d = j - j0;
        float bv = (d == 0) ? b0 : (d == 1) ? b1 : (d == 2) ? b2 : (d == 3) ? b3 : 0.0f;
        v[1 + j] = ok ? bv : 0.0f;
    }
}

__device__ __forceinline__ uint32_t smem_u32(const void* p) {
    uint32_t a;
    asm("{ .reg .u64 t; cvta.to.shared.u64 t, %1; cvt.u32.u64 %0, t; }" : "=r"(a) : "l"(p));
    return a;
}

__device__ __forceinline__ void cp16(uint32_t dst, const void* gsrc) {
    size_t p = __cvta_generic_to_global(const_cast<void*>(gsrc));
    asm volatile("cp.async.cg.shared.global [%0], [%1], 16;" :: "r"(dst), "l"(p) : "memory");
}
#define CP_COMMIT() asm volatile("cp.async.commit_group;" ::: "memory")
#define CP_WAIT1()  asm volatile("cp.async.wait_group 1;" ::: "memory")

__device__ __forceinline__ void ldm_x4(unsigned* d, uint32_t addr) {
    asm volatile("ldmatrix.sync.aligned.m8n8.x4.shared.b16 {%0,%1,%2,%3}, [%4];"
                 : "=r"(d[0]), "=r"(d[1]), "=r"(d[2]), "=r"(d[3]) : "r"(addr));
}

__device__ __forceinline__ void mma_f16(float* c, const unsigned* a,
                                        unsigned b0, unsigned b1) {
    asm volatile(
        "mma.sync.aligned.m16n8k16.row.col.f32.f16.f16.f32 "
        "{%0,%1,%2,%3}, {%4,%5,%6,%7}, {%8,%9}, {%0,%1,%2,%3};\n"
        : "+f"(c[0]), "+f"(c[1]), "+f"(c[2]), "+f"(c[3])
        : "r"(a[0]), "r"(a[1]), "r"(a[2]), "r"(a[3]), "r"(b0), "r"(b1));
}

// ---------------- prep kernels ----------------
__global__ void prep_w1h(const float* __restrict__ bw, const float* __restrict__ sw,
                         const float* __restrict__ sc) {
    int idx = blockIdx.x * 256 + threadIdx.x;   // o*H + i
    if (idx >= H * H) return;
    __half* dst = &g_W1h[(size_t)idx * 9];      // == o*KEXP + i*9
    dst[0] = __float2half_rn(bw[idx]);
    float s = sc[idx];
#pragma unroll
    for (int j = 0; j < 8; j++)
        dst[1 + j] = __float2half_rn(sw[(size_t)idx * 8 + j] * s);
}

__global__ void prep_w2(const float* __restrict__ bw, const float* __restrict__ sw,
                        const float* __restrict__ sc) {
    int i = blockIdx.x * 256 + threadIdx.x;
    if (i >= H) return;
    float s0 = sc[i], s1 = sc[H + i];
    g_W2c[i * 9] = make_float2(bw[i], bw[H + i]);
#pragma unroll
    for (int j = 0; j < 8; j++)
        g_W2c[i * 9 + 1 + j] = make_float2(sw[(size_t)i * 8 + j] * s0,
                                           sw[(size_t)(H + i) * 8 + j] * s1);
}

// ---------------- one-time spline expansion of the input ----------------
__global__ void expand_a(const float* __restrict__ x) {
    int idx = blockIdx.x * 256 + threadIdx.x;   // row*H + i
    float v[9];
    expand9(x[idx], v);
    __half* dst = &g_Aexp[(size_t)idx * 9];
#pragma unroll
    for (int j = 0; j < 9; j++) dst[j] = __float2half_rn(v[j]);
}

// ---------------- fused GEMM: layer1 + GELU + layer2-partials ----------------
__global__ void __launch_bounds__(256, 2) gemm_fused() {
    extern __shared__ __half sm[];
    const uint32_t sb = smem_u32(sm);
    const int tid = threadIdx.x, wid = tid >> 5, lane = tid & 31;
    const int g = lane >> 2, tg = lane & 3;
    const int wm = wid & 3, wn = wid >> 2;      // warp grid 4m x 2n, warp tile 32x64
    const int m0 = blockIdx.y * BM, n0 = blockIdx.x * BN;

    // ldmatrix per-thread address parts (bytes)
    const int r8 = lane & 7, sel = lane >> 3;
    const uint32_t a_off = ((wm * 32 + ((sel & 1) << 3) + r8) * PITCH + ((sel >> 1) << 3)) * 2;
    const uint32_t b_off = ((wn * 64 + ((sel >> 1) << 3) + r8) * PITCH + ((sel & 1) << 3)) * 2;

    float c[2][8][4];
#pragma unroll
    for (int mt = 0; mt < 2; mt++)
#pragma unroll
        for (int nt = 0; nt < 8; nt++)
#pragma unroll
            for (int q = 0; q < 4; q++) c[mt][nt][q] = 0.0f;

    auto issue = [&](int kt) {
        const uint32_t abase = sb + (kt % NSTAGE) * STGB;
        const __half* asrc = g_Aexp + (size_t)m0 * KEXP + kt * BK;
#pragma unroll
        for (int r = 0; r < 4; r++) {
            int ch = tid + r * 256;                 // 1024 chunks of 16B
            int row = ch >> 3, col = ch & 7;
            cp16(abase + row * ROWB + col * 16, asrc + (size_t)row * KEXP + col * 8);
        }
        const uint32_t bbase = abase + ASTGB;
        const __half* bsrc = g_W1h + (size_t)n0 * KEXP + kt * BK;
#pragma unroll
        for (int r = 0; r < 4; r++) {
            int ch = tid + r * 256;
            int row = ch >> 3, col = ch & 7;
            cp16(bbase + row * ROWB + col * 16, bsrc + (size_t)row * KEXP + col * 8);
        }
    };

    issue(0); CP_COMMIT();
    issue(1); CP_COMMIT();

    for (int kt = 0; kt < NKT; kt++) {
        CP_WAIT1();               // stage kt complete
        __syncthreads();          // everyone done reading stage (kt-1) == (kt+2)%3
        if (kt + 2 < NKT) issue(kt + 2);
        CP_COMMIT();

        const uint32_t sA = sb + (kt % NSTAGE) * STGB;
        const uint32_t sB = sA + ASTGB;
#pragma unroll
        for (int ks = 0; ks < 4; ks++) {
            unsigned a[2][4], b[4][4];
#pragma unroll
            for (int mt = 0; mt < 2; mt++)
                ldm_x4(a[mt], sA + a_off + mt * (16 * ROWB) + ks * 32);
#pragma unroll
            for (int np = 0; np < 4; np++)
                ldm_x4(b[np], sB + b_off + np * (16 * ROWB) + ks * 32);
#pragma unroll
            for (int nt = 0; nt < 8; nt++) {
                unsigned b0 = b[nt >> 1][(nt & 1) * 2];
                unsigned b1 = b[nt >> 1][(nt & 1) * 2 + 1];
#pragma unroll
                for (int mt = 0; mt < 2; mt++)
                    mma_f16(c[mt][nt], a[mt], b0, b1);
            }
        }
    }

    // epilogue: gelu + spline-expand + layer-2 partial dot (fp32)
    const int slice = blockIdx.x * 8 + wn * 4 + tg;
#pragma unroll
    for (int mt = 0; mt < 2; mt++) {
#pragma unroll
        for (int hq = 0; hq < 2; hq++) {
            int row = m0 + wm * 32 + mt * 16 + g + hq * 8;
            float p0 = 0.0f, p1 = 0.0f;
#pragma unroll
            for (int nt = 0; nt < 8; nt++) {
#pragma unroll
                for (int par = 0; par < 2; par++) {
                    float y = geluf(c[mt][nt][hq * 2 + par]);
                    int col = n0 + wn * 64 + nt * 8 + 2 * tg + par;
                    float v[9];
                    expand9(y, v);
                    const float2* w = &g_W2c[col * 9];
#pragma unroll
                    for (int j = 0; j < 9; j++) {
                        float2 wj = __ldg(&w[j]);
                        p0 = fmaf(v[j], wj.x, p0);
                        p1 = fmaf(v[j], wj.y, p1);
                    }
                }
            }
            g_part[(size_t)row * NSLICES + slice] = make_float2(p0, p1);
        }
    }
}

// ---------------- final reduce ----------------
__global__ void reduce2(float* __restrict__ out) {
    int row = blockIdx.x * 256 + threadIdx.x;
    if (row >= NROWS) return;
    const float2* p = &g_part[(size_t)row * NSLICES];
    float a = 0.0f, b = 0.0f;
#pragma unroll
    for (int s = 0; s < NSLICES; s++) { float2 v = p[s]; a += v.x; b += v.y; }
    out[row * 2 + 0] = a;
    out[row * 2 + 1] = b;
}

// ---------------------------------------------------------------------------
extern "C" void kernel_launch(void* const* d_in, const int* in_sizes, int n_in,
                              void* d_out, int out_size) {
    const float* hidden = (const float*)d_in[0];
    const float* bw1 = (const float*)d_in[1];
    const float* sw1 = (const float*)d_in[2];
    const float* sc1 = (const float*)d_in[3];
    const float* bw2 = (const float*)d_in[4];
    const float* sw2 = (const float*)d_in[5];
    const float* sc2 = (const float*)d_in[6];
    float* out = (float*)d_out;

    cudaFuncSetAttribute(gemm_fused, cudaFuncAttributeMaxDynamicSharedMemorySize, SMEMSZ);

    prep_w1h<<<(H * H + 255) / 256, 256>>>(bw1, sw1, sc1);
    prep_w2<<<(H + 255) / 256, 256>>>(bw2, sw2, sc2);
    expand_a<<<(NROWS * H) / 256, 256>>>(hidden);
    gemm_fused<<<dim3(NTILE, NROWS / BM), 256, SMEMSZ>>>();
    reduce2<<<NROWS / 256, 256>>>(out);
}